// round 11
// baseline (speedup 1.0000x reference)
#include <cuda_runtime.h>

// Problem constants (B=64, S=4096, D=256)
#define B_ 64
#define S_ 4096
#define D_ 256
#define NSPLIT 8
#define CHUNK (S_ / NSPLIT)            // 512 rows per block
#define NWARPS 8
#define THREADS 256
// Warp-private pipeline: warp owns 64 contiguous rows, streamed as 32 stages
// of 2 rows, double-buffered (DEPTH=2). Ring: 8 warps x 2 bufs x 2KB = 32KB.
#define STAGES 32
#define RING_F4 (NWARPS * 2 * 128)     // in float4 units

// Scratch: per (batch, split) partial accumulator + weight sum.
__device__ float g_acc[B_ * NSPLIT][D_];
__device__ float g_lsum[B_ * NSPLIT];
// Monotonic arrival counter per batch (mod NSPLIT detects last; replay-safe).
__device__ unsigned int g_cnt[B_];

// w = exp(tanh(x)) = e * exp(-2/(e^{2x}+1)); branch-free, robust at both tails.
__device__ __forceinline__ float exp_tanh(float x) {
    float t = __expf(2.0f * x);
    return 2.718281828f * __expf(__fdividef(-2.0f, t + 1.0f));
}

// 16-byte async copy, L2-only (streaming policy, bypasses L1).
__device__ __forceinline__ void cp16(float4* smem_dst, const float4* gsrc) {
    unsigned sa = (unsigned)__cvta_generic_to_shared(smem_dst);
    asm volatile("cp.async.cg.shared.global [%0], [%1], 16;\n" :: "r"(sa), "l"(gsrc));
}
#define CP_COMMIT()  asm volatile("cp.async.commit_group;\n" ::: "memory")
#define CP_WAIT(N)   asm volatile("cp.async.wait_group %0;\n" :: "n"(N) : "memory")

__global__ __launch_bounds__(THREADS) void att_fused(
    const float* __restrict__ aspect,   // [B, 1, D]
    const float* __restrict__ memory,   // [B, S, D]
    const float* __restrict__ W,        // [2D, 1]
    const float* __restrict__ bias,     // [1]
    float* __restrict__ out)            // [B, D]
{
    const int blk   = blockIdx.x;
    const int batch = blk / NSPLIT;
    const int split = blk % NSPLIT;
    const int tid   = threadIdx.x;
    const int warp  = tid >> 5;
    const int lane  = tid & 31;

    __shared__ float4 ring[RING_F4];    // 32KB
    __shared__ float s_red[NWARPS];
    __shared__ float s_abias;
    __shared__ float s_acc[D_];
    __shared__ float s_l[NWARPS];
    __shared__ unsigned int s_last;

    const float4* mem4 = (const float4*)memory
                       + (size_t)batch * (S_ * (D_ / 4))
                       + (size_t)split * CHUNK * (D_ / 4);
    // Warp w owns contiguous rows [64w, 64w+64) of the chunk.
    const float4* wbase = mem4 + (size_t)warp * 64 * (D_ / 4);

    // Self-consistent lane mapping: lane l copies AND reads float4 {l, 32+l}
    // of each row -> zero intra-warp races, no barriers in the stream loop.
    float4* b0 = ring + warp * 256 + lane;   // buf0: stage rows at +0,+32,+64,+96
    float4* b1 = b0 + 128;                   // buf1

    // ---- prologue: stage0 -> buf0 (rows 0,1), stage1 -> buf1 (rows 2,3) ----
    {
        const float4* s0 = wbase + lane;
        cp16(b0,      s0);       cp16(b0 + 32, s0 + 32);
        cp16(b0 + 64, s0 + 64);  cp16(b0 + 96, s0 + 96);
        CP_COMMIT();
        const float4* s1 = s0 + 128;
        cp16(b1,      s1);       cp16(b1 + 32, s1 + 32);
        cp16(b1 + 64, s1 + 64);  cp16(b1 + 96, s1 + 96);
        CP_COMMIT();
    }

    // ---- aspect bias: dot(aspect[batch], Wa) + b (overlaps prologue flight) ----
    {
        float p = aspect[batch * D_ + tid] * W[D_ + tid];
        #pragma unroll
        for (int o = 16; o; o >>= 1) p += __shfl_xor_sync(0xffffffffu, p, o);
        if (lane == 0) s_red[warp] = p;
    }
    s_acc[tid] = 0.0f;
    __syncthreads();
    if (tid == 0) {
        float s = bias[0];
        #pragma unroll
        for (int w = 0; w < NWARPS; w++) s += s_red[w];
        s_abias = s;
    }
    __syncthreads();
    const float abias = s_abias;

    // ---- Wm in registers: lane l holds W4[l] and W4[32+l] ----
    const float4* W4 = (const float4*)W;
    const float4 wm0 = W4[lane];
    const float4 wm1 = W4[32 + lane];

    float4 a0 = make_float4(0.f, 0.f, 0.f, 0.f);
    float4 a1 = make_float4(0.f, 0.f, 0.f, 0.f);
    float lsum = 0.0f;

    // Per-stage body: 2 rows (A = first row, B = second), ILP=2 chains.
    #define STAGE_BODY(PB)                                                      \
    {                                                                           \
        const float4 v0a = (PB)[0],  v1a = (PB)[32];                            \
        const float4 v0b = (PB)[64], v1b = (PB)[96];                            \
        float d0 = v0a.x*wm0.x + v0a.y*wm0.y + v0a.z*wm0.z + v0a.w*wm0.w        \
                 + v1a.x*wm1.x + v1a.y*wm1.y + v1a.z*wm1.z + v1a.w*wm1.w;       \
        float d1 = v0b.x*wm0.x + v0b.y*wm0.y + v0b.z*wm0.z + v0b.w*wm0.w        \
                 + v1b.x*wm1.x + v1b.y*wm1.y + v1b.z*wm1.z + v1b.w*wm1.w;       \
        _Pragma("unroll")                                                       \
        for (int o = 16; o; o >>= 1) {                                          \
            d0 += __shfl_xor_sync(0xffffffffu, d0, o);                          \
            d1 += __shfl_xor_sync(0xffffffffu, d1, o);                          \
        }                                                                       \
        const float w0 = exp_tanh(d0 + abias);                                  \
        const float w1 = exp_tanh(d1 + abias);                                  \
        lsum += w0 + w1;                                                        \
        a0.x += w0*v0a.x + w1*v0b.x;  a0.y += w0*v0a.y + w1*v0b.y;              \
        a0.z += w0*v0a.z + w1*v0b.z;  a0.w += w0*v0a.w + w1*v0b.w;              \
        a1.x += w0*v1a.x + w1*v1b.x;  a1.y += w0*v1a.y + w1*v1b.y;              \
        a1.z += w0*v1a.z + w1*v1b.z;  a1.w += w0*v1a.w + w1*v1b.w;              \
    }

    // ---- steady state: i = 0..29 — wait(1), compute stage i, refill its buf ----
    const float4* srcn = wbase + 256 + lane;   // stage i+2 source (advances 128/iter)
    #pragma unroll 2
    for (int i = 0; i < STAGES - 2; i++) {
        CP_WAIT(1);                            // stage i arrived (i+1 still flying)
        float4* pb = (i & 1) ? b1 : b0;        // constant under unroll 2
        STAGE_BODY(pb)
        cp16(pb,      srcn);       cp16(pb + 32, srcn + 32);   // stage i+2
        cp16(pb + 64, srcn + 64);  cp16(pb + 96, srcn + 96);
        CP_COMMIT();
        srcn += 128;
    }
    // ---- tail: stages 30 (buf0) and 31 (buf1); groups retire FIFO ----
    CP_WAIT(1);
    STAGE_BODY(b0)
    CP_WAIT(0);
    STAGE_BODY(b1)
    #undef STAGE_BODY

    // ---- combine 8 warps via smem atomics (one shot) ----
    atomicAdd(&s_acc[lane * 4 + 0], a0.x);
    atomicAdd(&s_acc[lane * 4 + 1], a0.y);
    atomicAdd(&s_acc[lane * 4 + 2], a0.z);
    atomicAdd(&s_acc[lane * 4 + 3], a0.w);
    atomicAdd(&s_acc[128 + lane * 4 + 0], a1.x);
    atomicAdd(&s_acc[128 + lane * 4 + 1], a1.y);
    atomicAdd(&s_acc[128 + lane * 4 + 2], a1.z);
    atomicAdd(&s_acc[128 + lane * 4 + 3], a1.w);
    if (lane == 0) s_l[warp] = lsum;
    __syncthreads();

    // ---- publish this block's partial ----
    g_acc[blk][tid] = s_acc[tid];
    if (tid == 0) {
        float l = 0.f;
        #pragma unroll
        for (int w = 0; w < NWARPS; w++) l += s_l[w];
        g_lsum[blk] = l;
    }

    // ---- last block of this batch combines (threadfence-reduction pattern) ----
    __threadfence();
    if (tid == 0) {
        unsigned int old = atomicAdd(&g_cnt[batch], 1u);
        s_last = (((old + 1u) % NSPLIT) == 0u) ? 1u : 0u;
    }
    __syncthreads();

    if (s_last) {
        float acc = 0.f, l = 0.f;
        #pragma unroll
        for (int sp = 0; sp < NSPLIT; sp++) {
            acc += g_acc[batch * NSPLIT + sp][tid];
            l   += g_lsum[batch * NSPLIT + sp];
        }
        out[batch * D_ + tid] = acc / l;
    }
}

extern "C" void kernel_launch(void* const* d_in, const int* in_sizes, int n_in,
                              void* d_out, int out_size)
{
    const float* aspect = (const float*)d_in[0];   // [B,1,D]
    const float* memory = (const float*)d_in[1];   // [B,S,D]
    const float* W      = (const float*)d_in[2];   // [2D,1]
    const float* bias   = (const float*)d_in[3];   // [1]
    float* out = (float*)d_out;                    // [B,D]

    att_fused<<<B_ * NSPLIT, THREADS>>>(aspect, memory, W, bias, out);
}